// round 16
// baseline (speedup 1.0000x reference)
#include <cuda_runtime.h>
#include <cuda_fp16.h>
#include <stdint.h>

// ===========================================================================
// Problem constants
// ===========================================================================
static constexpr int  Dd    = 384;
static constexpr long KTOT  = 147456;             // D*D

// Wide GEMM tiling (legacy HMMA path: mma.sync.m16n8k16, f32 accum)
static constexpr int NCHUNK = 2304;               // KTOT / 64
static constexpr int DEPTH  = 6;                  // B ring depth (== chunks per p)
static constexpr int PF     = 5;                  // prefetch distance
static constexpr int TILEB  = 48 * 128;           // 6144 B per B tile (contiguous)

// K-split: 16 slices of 24 p-values (144 chunks) each
static constexpr int KSPLIT = 16;
static constexpr int PSLICE = Dd / KSPLIT;        // 24
static constexpr int NWIDE  = 8 * 16 * KSPLIT;    // 2048 wide units

// fp16 copy of W_L2, TILED+SWIZZLED layout:
//   tile (T = n/48, c = chunk) at byte offset (T*NCHUNK + c)*6144
//   within tile: row r (=n%48), 16B seg s (=k/8 within chunk):
//   offset = r*128 + ((s ^ (r&7)) * 16)
__device__ __align__(16) __half g_W2h[113246208];

// per-K-slice partial accumulators (deterministic, no atomics): [16][1024][768]
__device__ __align__(16) float g_part[KSPLIT * 1024 * 768];

// per-(mt,nt) completion counters for the in-kernel reduction (self-resetting)
__device__ int g_cnt[128];

// ===========================================================================
// PTX helpers (baseline compute_103 features only: sm_90-era, no 'a')
// ===========================================================================
static __device__ __forceinline__ uint32_t smem_u32(const void* p) {
    uint32_t a;
    asm("{ .reg .u64 t; cvta.to.shared.u64 t, %1; cvt.u32.u64 %0, t; }" : "=r"(a) : "l"(p));
    return a;
}

#define MBAR_INIT(mbar, cnt) \
    asm volatile("mbarrier.init.shared.b64 [%0], %1;" \
                 :: "r"((uint32_t)(mbar)), "r"((uint32_t)(cnt)) : "memory")

#define MBAR_EXPECT_TX(mbar, bytes) \
    asm volatile("mbarrier.arrive.expect_tx.shared.b64 _, [%0], %1;" \
                 :: "r"((uint32_t)(mbar)), "r"((uint32_t)(bytes)) : "memory")

#define MBAR_ARRIVE(mbar) \
    asm volatile("mbarrier.arrive.shared.b64 _, [%0];" \
                 :: "r"((uint32_t)(mbar)) : "memory")

static __device__ __forceinline__ void mbar_wait(uint32_t mbar, uint32_t parity) {
    asm volatile(
        "{\n\t.reg .pred P;\n\t"
        "WL%=:\n\t"
        "mbarrier.try_wait.parity.acquire.cta.shared::cta.b64 P, [%0], %1;\n\t"
        "@!P bra WL%=;\n\t"
        "}"
        :: "r"(mbar), "r"(parity) : "memory");
}

static __device__ __forceinline__ void bulk_copy(uint32_t dst_smem, const void* src,
                                                 uint32_t bytes, uint32_t mbar) {
    asm volatile(
        "cp.async.bulk.shared::cta.global.mbarrier::complete_tx::bytes [%0], [%1], %2, [%3];"
        :: "r"(dst_smem), "l"(src), "r"(bytes), "r"(mbar) : "memory");
}

#define FENCE_PROXY_ASYNC() asm volatile("fence.proxy.async.shared::cta;" ::: "memory")

#define LDSM_X4(b0, b1, b2, b3, addr) \
    asm volatile("ldmatrix.sync.aligned.m8n8.x4.shared.b16 {%0,%1,%2,%3}, [%4];" \
                 : "=r"(b0), "=r"(b1), "=r"(b2), "=r"(b3) : "r"(addr))

#define MMA16816(d, a0, a1, a2, a3, b0, b1) \
    asm volatile("mma.sync.aligned.m16n8k16.row.col.f32.f16.f16.f32 " \
                 "{%0,%1,%2,%3}, {%4,%5,%6,%7}, {%8,%9}, {%0,%1,%2,%3};" \
                 : "+f"((d)[0]), "+f"((d)[1]), "+f"((d)[2]), "+f"((d)[3]) \
                 : "r"(a0), "r"(a1), "r"(a2), "r"(a3), "r"(b0), "r"(b1))

static __device__ __forceinline__ uint32_t h2u(__half2 v) {
    return *reinterpret_cast<uint32_t*>(&v);
}

// ===========================================================================
// Kernel 1: W_L2 f32 -> f16, TILED+SWIZZLED layout (pure streaming, 32 regs,
// measured 99 us @ 82% HBM peak — keep isolated, never fuse into it)
// ===========================================================================
__global__ __launch_bounds__(256) void convert_kernel(const float* __restrict__ W) {
    const long total = 768L * (KTOT / 8);          // 16B segs
    const long stride = (long)gridDim.x * blockDim.x;
    for (long g = (long)blockIdx.x * blockDim.x + threadIdx.x; g < total; g += stride) {
        int  n  = (int)(g / 18432);                // 18432 = KTOT/8
        int  ks = (int)(g - (long)n * 18432);
        int  c  = ks >> 3;
        int  s  = ks & 7;
        int  T  = n / 48;
        int  r  = n - T * 48;

        const float4* src = reinterpret_cast<const float4*>(
            W + (size_t)n * KTOT + ((size_t)c << 6) + (s << 3));
        float4 a = src[0];
        float4 b = src[1];
        uint4 v;
        v.x = h2u(__floats2half2_rn(a.x, a.y));
        v.y = h2u(__floats2half2_rn(a.z, a.w));
        v.z = h2u(__floats2half2_rn(b.x, b.y));
        v.w = h2u(__floats2half2_rn(b.z, b.w));

        size_t dst = (size_t)(T * NCHUNK + c) * TILEB
                   + (size_t)r * 128 + (size_t)((s ^ (r & 7)) << 4);
        *reinterpret_cast<uint4*>(reinterpret_cast<char*>(g_W2h) + dst) = v;
    }
}

// ===========================================================================
// Kernel 2: wide units (m-tile 128 x n-tile 48 x K-slice of 24 p-values).
//   A generated in registers; B via ONE cp.async.bulk per 64-k chunk.
//   mbarrier producer/consumer pipeline (no block barrier in the main loop).
//   Epilogue: store f32 partial; the LAST of the 16 slice-blocks per (mt,nt)
//   performs the bias + 16-way reduction (fixed order -> bitwise identical
//   to the old reduce kernel) and resets the counter for graph replay.
// ===========================================================================
__global__ __launch_bounds__(256, 1) void wide_kernel(const float* __restrict__ hs,
                                                      const float* __restrict__ ht,
                                                      const float* __restrict__ bL2,
                                                      float* __restrict__ out) {
    __shared__ __align__(16) char ring[DEPTH][TILEB];        // 36864 B
    __shared__ __align__(8)  unsigned long long mbar[2 * DEPTH];
    __shared__ int last_flag;

    const int tid  = threadIdx.x;
    const int wid  = tid >> 5;
    const int lane = tid & 31;

    // blockIdx = ((ksl*16 + nt)*8 + mt): consecutive ids share the B slice
    const int mt   = blockIdx.x & 7;
    const int rest = blockIdx.x >> 3;
    const int nt   = rest & 15;
    const int ksl  = rest >> 4;
    const int n0   = nt * 48;
    const int p0   = ksl * PSLICE;
    const int CBEG = p0 * 6;
    const int CEND = (p0 + PSLICE) * 6;

    // this thread's two A rows (mma m16n8k16 fragment rows)
    const int r0 = mt * 128 + wid * 16 + (lane >> 2);
    const int r1 = r0 + 8;
    const int qo = 2 * (lane & 3);           // fragment k offset within k16

    const uint32_t ring0 = smem_u32(ring[0]);
    const uint32_t fmb0  = smem_u32(&mbar[0]);          // full[0..5]
    const uint32_t emb0  = fmb0 + DEPTH * 8;            // empty[0..5]

    if (tid == 0) {
#pragma unroll
        for (int s = 0; s < DEPTH; s++) {
            MBAR_INIT(fmb0 + s * 8, 1);
            MBAR_INIT(emb0 + s * 8, 8);
        }
    }
    FENCE_PROXY_ASYNC();
    __syncthreads();

    // B tile source base for this n-tile (tiled+swizzled layout)
    const char* Wt = reinterpret_cast<const char*>(g_W2h) + (size_t)nt * NCHUNK * TILEB;

    // prologue: prefetch chunks CBEG..CBEG+PF-1 into slots 0..PF-1 (all fresh)
    if (tid == 0) {
#pragma unroll
        for (int c = 0; c < PF; c++) {
            MBAR_EXPECT_TX(fmb0 + c * 8, TILEB);
            bulk_copy(ring0 + c * TILEB, Wt + (size_t)(CBEG + c) * TILEB,
                      TILEB, fmb0 + c * 8);
        }
    }

    // ---- resident ht fragments in registers: 2 rows x 24 blocks x 2 half2 ----
    __half2 htA[48], htB[48];
    {
        const float* htr0 = ht + (size_t)r0 * Dd;
        const float* htr1 = ht + (size_t)r1 * Dd;
#pragma unroll
        for (int blk = 0; blk < 24; blk++) {
            float2 f;
            f = *reinterpret_cast<const float2*>(htr0 + blk * 16 + qo);
            htA[blk * 2 + 0] = __floats2half2_rn(f.x, f.y);
            f = *reinterpret_cast<const float2*>(htr0 + blk * 16 + qo + 8);
            htA[blk * 2 + 1] = __floats2half2_rn(f.x, f.y);
            f = *reinterpret_cast<const float2*>(htr1 + blk * 16 + qo);
            htB[blk * 2 + 0] = __floats2half2_rn(f.x, f.y);
            f = *reinterpret_cast<const float2*>(htr1 + blk * 16 + qo + 8);
            htB[blk * 2 + 1] = __floats2half2_rn(f.x, f.y);
        }
    }

    float acc[6][4];
#pragma unroll
    for (int t = 0; t < 6; t++)
#pragma unroll
        for (int c = 0; c < 4; c++) acc[t][c] = 0.0f;

    // ldmatrix lane addressing (swizzled layout): row base + seg^row XOR
    const uint32_t rowoff = (uint32_t)((lane & 7) * 128);
    const uint32_t x0 = (uint32_t)((((lane >> 3)    ) ^ (lane & 7)) * 16);
    const uint32_t x1 = (uint32_t)((((lane >> 3) + 4) ^ (lane & 7)) * 16);

    const float* hsr0 = hs + (size_t)r0 * Dd;
    const float* hsr1 = hs + (size_t)r1 * Dd;

    // ---- main loop: 24 p values x 6 chunks of 64 q (no block barrier) ----
    for (int pp = 0; pp < PSLICE; pp++) {
        const int p = p0 + pp;
        __half2 h0 = __half2half2(__float2half_rn(__ldg(hsr0 + p)));
        __half2 h1 = __half2half2(__float2half_rn(__ldg(hsr1 + p)));
        const uint32_t par = (uint32_t)(pp & 1);

#pragma unroll
        for (int c2 = 0; c2 < 6; c2++) {
            const int i = p * 6 + c2;            // global chunk; i % 6 == c2

            // A fragments for 4 k16-steps (pure register math, no waits)
            uint32_t a[4][4];
#pragma unroll
            for (int s = 0; s < 4; s++) {
                const int blk = c2 * 4 + s;
                a[s][0] = h2u(__hmul2(h0, htA[blk * 2 + 0]));  // row r0, k lo
                a[s][1] = h2u(__hmul2(h1, htB[blk * 2 + 0]));  // row r1, k lo
                a[s][2] = h2u(__hmul2(h0, htA[blk * 2 + 1]));  // row r0, k hi
                a[s][3] = h2u(__hmul2(h1, htB[blk * 2 + 1]));  // row r1, k hi
            }

            // producer: issue chunk i+PF into slot (c2+PF)%6 once that slot's
            // previous consumers have all arrived on empty[]
            if (tid == 0) {
                const int nc = i + PF;
                if (nc < CEND) {
                    const int sl = (c2 + PF) % DEPTH;   // == nc % 6
                    if (!(pp == 0 && c2 == 0)) {
                        // empty parity: (use#-1)&1 -> par for c2>=1, par^1 for c2==0
                        const uint32_t ep = (c2 == 0) ? (par ^ 1u) : par;
                        mbar_wait(emb0 + sl * 8, ep);
                    }
                    MBAR_EXPECT_TX(fmb0 + sl * 8, TILEB);
                    bulk_copy(ring0 + sl * TILEB, Wt + (size_t)nc * TILEB,
                              TILEB, fmb0 + sl * 8);
                }
            }

            // consumer: wait B tile for chunk i (phase = pp)
            mbar_wait(fmb0 + c2 * 8, par);

            const uint32_t sbase = ring0 + (uint32_t)(c2 * TILEB) + rowoff;
#pragma unroll
            for (int t = 0; t < 6; t++) {
                uint32_t b0, b1, b2, b3, b4, b5, b6, b7;
                LDSM_X4(b0, b1, b2, b3, sbase + (uint32_t)(t * 1024) + x0); // ksteps 0,1
                LDSM_X4(b4, b5, b6, b7, sbase + (uint32_t)(t * 1024) + x1); // ksteps 2,3
                MMA16816(acc[t], a[0][0], a[0][1], a[0][2], a[0][3], b0, b1);
                MMA16816(acc[t], a[1][0], a[1][1], a[1][2], a[1][3], b2, b3);
                MMA16816(acc[t], a[2][0], a[2][1], a[2][2], a[2][3], b4, b5);
                MMA16816(acc[t], a[3][0], a[3][1], a[3][2], a[3][3], b6, b7);
            }

            // this warp is done reading slot c2 for this phase
            if (lane == 0) MBAR_ARRIVE(emb0 + c2 * 8);
        }
    }

    // ---- epilogue: store f32 partial into g_part[ksl] (deterministic) ----
    float* pb = g_part + (size_t)ksl * (1024 * 768);
#pragma unroll
    for (int t = 0; t < 6; t++) {
        const int n = n0 + t * 8 + qo;
        *reinterpret_cast<float2*>(pb + (size_t)r0 * 768 + n) =
            make_float2(acc[t][0], acc[t][1]);
        *reinterpret_cast<float2*>(pb + (size_t)r1 * 768 + n) =
            make_float2(acc[t][2], acc[t][3]);
    }

    // ---- last-slice-reduces: 16th block for this (mt,nt) sums partials ----
    __syncthreads();
    __threadfence();
    const int cidx = mt * 16 + nt;
    if (tid == 0) {
        int old = atomicAdd(&g_cnt[cidx], 1);
        last_flag = (old == 15);
    }
    __syncthreads();
    if (!last_flag) return;
    __threadfence();   // order counter-read before partial loads

    // this block reduces its 128x48 tile: 1536 float4 outputs, 6 per thread
    const int m0 = mt * 128;
#pragma unroll
    for (int e = 0; e < 6; e++) {
        const int o  = tid + e * 256;          // 0..1535
        const int rr = o / 12;                 // row 0..127
        const int c4 = o - rr * 12;            // float4 col 0..11
        const int n  = n0 + c4 * 4;

        float4 s = *reinterpret_cast<const float4*>(bL2 + n);
#pragma unroll
        for (int k = 0; k < KSPLIT; k++) {
            const float4 v = *reinterpret_cast<const float4*>(
                g_part + (size_t)k * (1024 * 768) + (size_t)(m0 + rr) * 768 + n);
            s.x += v.x; s.y += v.y; s.z += v.z; s.w += v.w;
        }
        *reinterpret_cast<float4*>(out + (size_t)(m0 + rr) * 1536 + 768 + n) = s;
    }

    // reset counter for the next graph replay (single writer, post-reduction)
    __syncthreads();
    if (tid == 0) g_cnt[cidx] = 0;
}

// ===========================================================================
// Kernel 3: deep path g = cat(hs,ht) @ W_L^T + b_L  (exact f32, 64x64 tiles)
// grid = (16, 12), 256 threads — standalone to avoid codegen contamination
// ===========================================================================
__global__ __launch_bounds__(256) void deep_kernel(const float* __restrict__ hs,
                                                   const float* __restrict__ ht,
                                                   const float* __restrict__ WL,
                                                   const float* __restrict__ bL,
                                                   float* __restrict__ out) {
    __shared__ float As[16][64];
    __shared__ float Bs[16][64];
    const int tid = threadIdx.x;
    const int m0 = blockIdx.x * 64;
    const int n0 = blockIdx.y * 64;
    const int ty = tid >> 4;
    const int tx = tid & 15;

    float acc[4][4] = {};

    for (int kk = 0; kk < 768; kk += 16) {
#pragma unroll
        for (int l = 0; l < 4; l++) {
            int i = tid + l * 256;
            int r = i >> 4;
            int c = i & 15;
            int k = kk + c;
            float av = (k < 384) ? hs[(size_t)(m0 + r) * 384 + k]
                                 : ht[(size_t)(m0 + r) * 384 + (k - 384)];
            As[c][r] = av;
            Bs[c][r] = WL[(size_t)(n0 + r) * 768 + k];
        }
        __syncthreads();
#pragma unroll
        for (int k = 0; k < 16; k++) {
            float4 a4 = *reinterpret_cast<const float4*>(&As[k][ty * 4]);
            float4 b4 = *reinterpret_cast<const float4*>(&Bs[k][tx * 4]);
            float a[4] = {a4.x, a4.y, a4.z, a4.w};
            float b[4] = {b4.x, b4.y, b4.z, b4.w};
#pragma unroll
            for (int i2 = 0; i2 < 4; i2++)
#pragma unroll
                for (int j = 0; j < 4; j++) acc[i2][j] += a[i2] * b[j];
        }
        __syncthreads();
    }

#pragma unroll
    for (int i2 = 0; i2 < 4; i2++) {
        int m = m0 + ty * 4 + i2;
#pragma unroll
        for (int j = 0; j < 4; j++) {
            int n = n0 + tx * 4 + j;
            out[(size_t)m * 1536 + n] = acc[i2][j] + bL[n];
        }
    }
}

// ===========================================================================
// kernel_launch
// Inputs (metadata order): hspatial, htext, W_L, b_L, W_L2, b_L2. Output f32.
// ===========================================================================
extern "C" void kernel_launch(void* const* d_in, const int* in_sizes, int n_in,
                              void* d_out, int out_size) {
    const float* hs  = (const float*)d_in[0];
    const float* ht  = (const float*)d_in[1];
    const float* WL  = (const float*)d_in[2];
    const float* bL  = (const float*)d_in[3];
    const float* WL2 = (const float*)d_in[4];
    const float* bL2 = (const float*)d_in[5];
    float* out = (float*)d_out;

    // 1) W_L2 -> fp16 scratch, tiled+swizzled (pure streaming, ~99 us)
    convert_kernel<<<2048, 256>>>(WL2);

    // 2) wide path: 2048 K-slice units, mbarrier pipeline, in-kernel reduction
    wide_kernel<<<NWIDE, 256>>>(hs, ht, bL2, out);

    // 3) deep path (exact f32, standalone)
    dim3 dgrid(16, 12);
    deep_kernel<<<dgrid, 256>>>(hs, ht, WL, bL, out);
}

// round 17
// speedup vs baseline: 1.1132x; 1.1132x over previous
#include <cuda_runtime.h>
#include <cuda_fp16.h>
#include <stdint.h>

// ===========================================================================
// Problem constants
// ===========================================================================
static constexpr int  Dd    = 384;
static constexpr long KTOT  = 147456;             // D*D

// Wide GEMM tiling (legacy HMMA path: mma.sync.m16n8k16, f32 accum)
static constexpr int NCHUNK = 2304;               // KTOT / 64
static constexpr int DEPTH  = 6;                  // B ring depth (== chunks per p)
static constexpr int PF     = 5;                  // prefetch distance
static constexpr int TILEB  = 48 * 128;           // 6144 B per B tile (contiguous)

// K-split: 16 slices of 24 p-values (144 chunks) each
static constexpr int KSPLIT = 16;
static constexpr int PSLICE = Dd / KSPLIT;        // 24
static constexpr int NWIDE  = 8 * 16 * KSPLIT;    // 2048 wide units

// fp16 copy of W_L2, TILED+SWIZZLED layout:
//   tile (T = n/48, c = chunk) at byte offset (T*NCHUNK + c)*6144
//   within tile: row r (=n%48), 16B seg s (=k/8 within chunk):
//   offset = r*128 + ((s ^ (r&7)) * 16)
__device__ __align__(16) __half g_W2h[113246208];

// per-K-slice partial accumulators (deterministic, no atomics): [16][1024][768]
__device__ __align__(16) float g_part[KSPLIT * 1024 * 768];

// ===========================================================================
// PTX helpers (baseline compute_103 features only: sm_90-era, no 'a')
// ===========================================================================
static __device__ __forceinline__ uint32_t smem_u32(const void* p) {
    uint32_t a;
    asm("{ .reg .u64 t; cvta.to.shared.u64 t, %1; cvt.u32.u64 %0, t; }" : "=r"(a) : "l"(p));
    return a;
}

#define MBAR_INIT(mbar, cnt) \
    asm volatile("mbarrier.init.shared.b64 [%0], %1;" \
                 :: "r"((uint32_t)(mbar)), "r"((uint32_t)(cnt)) : "memory")

#define MBAR_EXPECT_TX(mbar, bytes) \
    asm volatile("mbarrier.arrive.expect_tx.shared.b64 _, [%0], %1;" \
                 :: "r"((uint32_t)(mbar)), "r"((uint32_t)(bytes)) : "memory")

#define MBAR_ARRIVE(mbar) \
    asm volatile("mbarrier.arrive.shared.b64 _, [%0];" \
                 :: "r"((uint32_t)(mbar)) : "memory")

static __device__ __forceinline__ void mbar_wait(uint32_t mbar, uint32_t parity) {
    asm volatile(
        "{\n\t.reg .pred P;\n\t"
        "WL%=:\n\t"
        "mbarrier.try_wait.parity.acquire.cta.shared::cta.b64 P, [%0], %1;\n\t"
        "@!P bra WL%=;\n\t"
        "}"
        :: "r"(mbar), "r"(parity) : "memory");
}

static __device__ __forceinline__ void bulk_copy(uint32_t dst_smem, const void* src,
                                                 uint32_t bytes, uint32_t mbar) {
    asm volatile(
        "cp.async.bulk.shared::cta.global.mbarrier::complete_tx::bytes [%0], [%1], %2, [%3];"
        :: "r"(dst_smem), "l"(src), "r"(bytes), "r"(mbar) : "memory");
}

#define FENCE_PROXY_ASYNC() asm volatile("fence.proxy.async.shared::cta;" ::: "memory")

#define LDSM_X4(b0, b1, b2, b3, addr) \
    asm volatile("ldmatrix.sync.aligned.m8n8.x4.shared.b16 {%0,%1,%2,%3}, [%4];" \
                 : "=r"(b0), "=r"(b1), "=r"(b2), "=r"(b3) : "r"(addr))

#define MMA16816(d, a0, a1, a2, a3, b0, b1) \
    asm volatile("mma.sync.aligned.m16n8k16.row.col.f32.f16.f16.f32 " \
                 "{%0,%1,%2,%3}, {%4,%5,%6,%7}, {%8,%9}, {%0,%1,%2,%3};" \
                 : "+f"((d)[0]), "+f"((d)[1]), "+f"((d)[2]), "+f"((d)[3]) \
                 : "r"(a0), "r"(a1), "r"(a2), "r"(a3), "r"(b0), "r"(b1))

static __device__ __forceinline__ uint32_t h2u(__half2 v) {
    return *reinterpret_cast<uint32_t*>(&v);
}

// ===========================================================================
// Kernel 1: W_L2 f32 -> f16, TILED+SWIZZLED layout (pure streaming, 32 regs,
// measured 98 us @ 82% HBM peak — keep isolated, never fuse into it)
// ===========================================================================
__global__ __launch_bounds__(256) void convert_kernel(const float* __restrict__ W) {
    const long total = 768L * (KTOT / 8);          // 16B segs
    const long stride = (long)gridDim.x * blockDim.x;
    for (long g = (long)blockIdx.x * blockDim.x + threadIdx.x; g < total; g += stride) {
        int  n  = (int)(g / 18432);                // 18432 = KTOT/8
        int  ks = (int)(g - (long)n * 18432);
        int  c  = ks >> 3;
        int  s  = ks & 7;
        int  T  = n / 48;
        int  r  = n - T * 48;

        const float4* src = reinterpret_cast<const float4*>(
            W + (size_t)n * KTOT + ((size_t)c << 6) + (s << 3));
        float4 a = src[0];
        float4 b = src[1];
        uint4 v;
        v.x = h2u(__floats2half2_rn(a.x, a.y));
        v.y = h2u(__floats2half2_rn(a.z, a.w));
        v.z = h2u(__floats2half2_rn(b.x, b.y));
        v.w = h2u(__floats2half2_rn(b.z, b.w));

        size_t dst = (size_t)(T * NCHUNK + c) * TILEB
                   + (size_t)r * 128 + (size_t)((s ^ (r & 7)) << 4);
        *reinterpret_cast<uint4*>(reinterpret_cast<char*>(g_W2h) + dst) = v;
    }
}

// ===========================================================================
// Kernel 2: wide units (m-tile 128 x n-tile 48 x K-slice of 24 p-values).
//   A generated in registers; B via ONE cp.async.bulk per 64-k chunk.
//   Producer/consumer mbarrier pipeline — NO block barrier in the main loop.
//   f32 partials -> g_part[ksl] (deterministic, no atomics).
// ===========================================================================
__global__ __launch_bounds__(256, 1) void wide_kernel(const float* __restrict__ hs,
                                                      const float* __restrict__ ht) {
    __shared__ __align__(16) char ring[DEPTH][TILEB];        // 36864 B
    __shared__ __align__(8)  unsigned long long mbar[2 * DEPTH];

    const int tid  = threadIdx.x;
    const int wid  = tid >> 5;
    const int lane = tid & 31;

    // blockIdx = ((ksl*16 + nt)*8 + mt): consecutive ids share the B slice
    const int mt   = blockIdx.x & 7;
    const int rest = blockIdx.x >> 3;
    const int nt   = rest & 15;
    const int ksl  = rest >> 4;
    const int n0   = nt * 48;
    const int p0   = ksl * PSLICE;
    const int CBEG = p0 * 6;
    const int CEND = (p0 + PSLICE) * 6;

    // this thread's two A rows (mma m16n8k16 fragment rows)
    const int r0 = mt * 128 + wid * 16 + (lane >> 2);
    const int r1 = r0 + 8;
    const int qo = 2 * (lane & 3);           // fragment k offset within k16

    const uint32_t ring0 = smem_u32(ring[0]);
    const uint32_t fmb0  = smem_u32(&mbar[0]);          // full[0..5]
    const uint32_t emb0  = fmb0 + DEPTH * 8;            // empty[0..5]

    if (tid == 0) {
#pragma unroll
        for (int s = 0; s < DEPTH; s++) {
            MBAR_INIT(fmb0 + s * 8, 1);
            MBAR_INIT(emb0 + s * 8, 8);
        }
    }
    FENCE_PROXY_ASYNC();
    __syncthreads();

    // B tile source base for this n-tile (tiled+swizzled layout)
    const char* Wt = reinterpret_cast<const char*>(g_W2h) + (size_t)nt * NCHUNK * TILEB;

    // prologue: prefetch chunks CBEG..CBEG+PF-1 into slots 0..PF-1 (all fresh)
    if (tid == 0) {
#pragma unroll
        for (int c = 0; c < PF; c++) {
            MBAR_EXPECT_TX(fmb0 + c * 8, TILEB);
            bulk_copy(ring0 + c * TILEB, Wt + (size_t)(CBEG + c) * TILEB,
                      TILEB, fmb0 + c * 8);
        }
    }

    // ---- resident ht fragments in registers: 2 rows x 24 blocks x 2 half2 ----
    __half2 htA[48], htB[48];
    {
        const float* htr0 = ht + (size_t)r0 * Dd;
        const float* htr1 = ht + (size_t)r1 * Dd;
#pragma unroll
        for (int blk = 0; blk < 24; blk++) {
            float2 f;
            f = *reinterpret_cast<const float2*>(htr0 + blk * 16 + qo);
            htA[blk * 2 + 0] = __floats2half2_rn(f.x, f.y);
            f = *reinterpret_cast<const float2*>(htr0 + blk * 16 + qo + 8);
            htA[blk * 2 + 1] = __floats2half2_rn(f.x, f.y);
            f = *reinterpret_cast<const float2*>(htr1 + blk * 16 + qo);
            htB[blk * 2 + 0] = __floats2half2_rn(f.x, f.y);
            f = *reinterpret_cast<const float2*>(htr1 + blk * 16 + qo + 8);
            htB[blk * 2 + 1] = __floats2half2_rn(f.x, f.y);
        }
    }

    float acc[6][4];
#pragma unroll
    for (int t = 0; t < 6; t++)
#pragma unroll
        for (int c = 0; c < 4; c++) acc[t][c] = 0.0f;

    // ldmatrix lane addressing (swizzled layout): row base + seg^row XOR
    const uint32_t rowoff = (uint32_t)((lane & 7) * 128);
    const uint32_t x0 = (uint32_t)((((lane >> 3)    ) ^ (lane & 7)) * 16);
    const uint32_t x1 = (uint32_t)((((lane >> 3) + 4) ^ (lane & 7)) * 16);

    const float* hsr0 = hs + (size_t)r0 * Dd;
    const float* hsr1 = hs + (size_t)r1 * Dd;

    // ---- main loop: 24 p values x 6 chunks of 64 q (no block barrier) ----
    for (int pp = 0; pp < PSLICE; pp++) {
        const int p = p0 + pp;
        __half2 h0 = __half2half2(__float2half_rn(__ldg(hsr0 + p)));
        __half2 h1 = __half2half2(__float2half_rn(__ldg(hsr1 + p)));
        const uint32_t par = (uint32_t)(pp & 1);

#pragma unroll
        for (int c2 = 0; c2 < 6; c2++) {
            const int i = p * 6 + c2;            // global chunk; i % 6 == c2

            // A fragments for 4 k16-steps (pure register math, no waits)
            uint32_t a[4][4];
#pragma unroll
            for (int s = 0; s < 4; s++) {
                const int blk = c2 * 4 + s;
                a[s][0] = h2u(__hmul2(h0, htA[blk * 2 + 0]));  // row r0, k lo
                a[s][1] = h2u(__hmul2(h1, htB[blk * 2 + 0]));  // row r1, k lo
                a[s][2] = h2u(__hmul2(h0, htA[blk * 2 + 1]));  // row r0, k hi
                a[s][3] = h2u(__hmul2(h1, htB[blk * 2 + 1]));  // row r1, k hi
            }

            // producer: issue chunk i+PF into slot (c2+PF)%6 once that slot's
            // previous consumers have all arrived on empty[]
            if (tid == 0) {
                const int nc = i + PF;
                if (nc < CEND) {
                    const int sl = (c2 + PF) % DEPTH;   // == nc % 6
                    if (!(pp == 0 && c2 == 0)) {
                        // empty parity: (use#-1)&1 -> par for c2>=1, par^1 for c2==0
                        const uint32_t ep = (c2 == 0) ? (par ^ 1u) : par;
                        mbar_wait(emb0 + sl * 8, ep);
                    }
                    MBAR_EXPECT_TX(fmb0 + sl * 8, TILEB);
                    bulk_copy(ring0 + sl * TILEB, Wt + (size_t)nc * TILEB,
                              TILEB, fmb0 + sl * 8);
                }
            }

            // consumer: wait B tile for chunk i (phase = pp)
            mbar_wait(fmb0 + c2 * 8, par);

            const uint32_t sbase = ring0 + (uint32_t)(c2 * TILEB) + rowoff;
#pragma unroll
            for (int t = 0; t < 6; t++) {
                uint32_t b0, b1, b2, b3, b4, b5, b6, b7;
                LDSM_X4(b0, b1, b2, b3, sbase + (uint32_t)(t * 1024) + x0); // ksteps 0,1
                LDSM_X4(b4, b5, b6, b7, sbase + (uint32_t)(t * 1024) + x1); // ksteps 2,3
                MMA16816(acc[t], a[0][0], a[0][1], a[0][2], a[0][3], b0, b1);
                MMA16816(acc[t], a[1][0], a[1][1], a[1][2], a[1][3], b2, b3);
                MMA16816(acc[t], a[2][0], a[2][1], a[2][2], a[2][3], b4, b5);
                MMA16816(acc[t], a[3][0], a[3][1], a[3][2], a[3][3], b6, b7);
            }

            // this warp is done reading slot c2 for this phase
            if (lane == 0) MBAR_ARRIVE(emb0 + c2 * 8);
        }
    }

    // ---- epilogue: store f32 partial into g_part[ksl] (deterministic) ----
    float* pb = g_part + (size_t)ksl * (1024 * 768);
#pragma unroll
    for (int t = 0; t < 6; t++) {
        const int n = n0 + t * 8 + qo;
        *reinterpret_cast<float2*>(pb + (size_t)r0 * 768 + n) =
            make_float2(acc[t][0], acc[t][1]);
        *reinterpret_cast<float2*>(pb + (size_t)r1 * 768 + n) =
            make_float2(acc[t][2], acc[t][3]);
    }
}

// ===========================================================================
// Kernel 3: deep path g = cat(hs,ht) @ W_L^T + b_L  (exact f32, 64x64 tiles)
// grid = (16, 12), 256 threads — runs on a side stream, overlapped with the
// convert pass (complementary pipes: FFMA vs DRAM)
// ===========================================================================
__global__ __launch_bounds__(256) void deep_kernel(const float* __restrict__ hs,
                                                   const float* __restrict__ ht,
                                                   const float* __restrict__ WL,
                                                   const float* __restrict__ bL,
                                                   float* __restrict__ out) {
    __shared__ float As[16][64];
    __shared__ float Bs[16][64];
    const int tid = threadIdx.x;
    const int m0 = blockIdx.x * 64;
    const int n0 = blockIdx.y * 64;
    const int ty = tid >> 4;
    const int tx = tid & 15;

    float acc[4][4] = {};

    for (int kk = 0; kk < 768; kk += 16) {
#pragma unroll
        for (int l = 0; l < 4; l++) {
            int i = tid + l * 256;
            int r = i >> 4;
            int c = i & 15;
            int k = kk + c;
            float av = (k < 384) ? hs[(size_t)(m0 + r) * 384 + k]
                                 : ht[(size_t)(m0 + r) * 384 + (k - 384)];
            As[c][r] = av;
            Bs[c][r] = WL[(size_t)(n0 + r) * 768 + k];
        }
        __syncthreads();
#pragma unroll
        for (int k = 0; k < 16; k++) {
            float4 a4 = *reinterpret_cast<const float4*>(&As[k][ty * 4]);
            float4 b4 = *reinterpret_cast<const float4*>(&Bs[k][tx * 4]);
            float a[4] = {a4.x, a4.y, a4.z, a4.w};
            float b[4] = {b4.x, b4.y, b4.z, b4.w};
#pragma unroll
            for (int i2 = 0; i2 < 4; i2++)
#pragma unroll
                for (int j = 0; j < 4; j++) acc[i2][j] += a[i2] * b[j];
        }
        __syncthreads();
    }

#pragma unroll
    for (int i2 = 0; i2 < 4; i2++) {
        int m = m0 + ty * 4 + i2;
#pragma unroll
        for (int j = 0; j < 4; j++) {
            int n = n0 + tx * 4 + j;
            out[(size_t)m * 1536 + n] = acc[i2][j] + bL[n];
        }
    }
}

// ===========================================================================
// Kernel 4: out[:,768:1536] = bias + sum over 16 K-slices of g_part
// grid = 768, block = 256; one float4 per thread (196608 float4 elements)
// ===========================================================================
__global__ __launch_bounds__(256) void reduce_kernel(const float* __restrict__ bL2,
                                                     float* __restrict__ out) {
    const int e4 = blockIdx.x * 256 + threadIdx.x;   // 0..196607
    const int b  = e4 / 192;                          // row
    const int n4 = e4 - b * 192;                      // float4 col
    const int n  = n4 * 4;

    float4 s = *reinterpret_cast<const float4*>(bL2 + n);
#pragma unroll
    for (int k = 0; k < KSPLIT; k++) {
        const float4 v = *reinterpret_cast<const float4*>(
            g_part + (size_t)k * (1024 * 768) + (size_t)b * 768 + n);
        s.x += v.x; s.y += v.y; s.z += v.z; s.w += v.w;
    }
    *reinterpret_cast<float4*>(out + (size_t)b * 1536 + 768 + n) = s;
}

// ===========================================================================
// kernel_launch
// Inputs (metadata order): hspatial, htext, W_L, b_L, W_L2, b_L2. Output f32.
// Deep path runs on a side stream, overlapped with the convert pass
// (fork/join via events — graph-capture legal).
// ===========================================================================
extern "C" void kernel_launch(void* const* d_in, const int* in_sizes, int n_in,
                              void* d_out, int out_size) {
    const float* hs  = (const float*)d_in[0];
    const float* ht  = (const float*)d_in[1];
    const float* WL  = (const float*)d_in[2];
    const float* bL  = (const float*)d_in[3];
    const float* WL2 = (const float*)d_in[4];
    const float* bL2 = (const float*)d_in[5];
    float* out = (float*)d_out;

    static cudaStream_t s2 = nullptr;
    static cudaEvent_t evFork = nullptr, evJoin = nullptr;
    if (s2 == nullptr) {
        cudaStreamCreateWithFlags(&s2, cudaStreamNonBlocking);
        cudaEventCreateWithFlags(&evFork, cudaEventDisableTiming);
        cudaEventCreateWithFlags(&evJoin, cudaEventDisableTiming);
    }

    // fork: deep path on side stream, concurrent with convert
    cudaEventRecord(evFork, 0);
    cudaStreamWaitEvent(s2, evFork, 0);
    dim3 dgrid(16, 12);
    deep_kernel<<<dgrid, 256, 0, s2>>>(hs, ht, WL, bL, out);
    cudaEventRecord(evJoin, s2);

    // main stream: convert -> wide -> reduce
    convert_kernel<<<2048, 256>>>(WL2);
    wide_kernel<<<NWIDE, 256>>>(hs, ht);
    reduce_kernel<<<768, 256>>>(bL2, out);

    // join: main stream completes only after deep has finished
    cudaStreamWaitEvent(0, evJoin, 0);
}